// round 17
// baseline (speedup 1.0000x reference)
#include <cuda_runtime.h>
#include <cuda_fp16.h>
#include <stdint.h>

// Problem constants
#define B_TOT   4096
#define T_      64
#define D_      250
#define K_      1000
#define H_      125
#define NT      4
#define NL      50

// Tiling
#define BM      32
#define BN      128
#define KCH     128
#define NCHUNK  8
#define THREADS 512

// smem layout (bytes)
#define OFF_A    0                    // [buf2][8192] fp16 A -> 16384
#define OFF_B    16384                // [buf3][32768] -> 98304
#define OFF_SOFF 114688               // 32*4 ints
#define SMEM_TOTAL (114688 + 512)
// epilogue reuse:
#define OFF_RS   OFF_A                // reduction buffers (<=16KB)
#define OFF_HF   OFF_B                // Hs fp16 [2 panels][32x128B] = 8192
#define OFF_W2I  (OFF_B + 8192)       // W2 fp16 image [128][128B] = 16384

#define SW128(x) ((x) ^ ((((uint32_t)(x)) >> 3) & 0x70))

// Pre-swizzled W1 fp16 images: [half][chunk8][kpanel2][npanel2][8192]
__device__ __align__(16) uint8_t g_wbf[(size_t)2 * 8 * 32768];
// Pre-swizzled W2 fp16 images: [half][128 rows x 128B] = 2 x 16KB
__device__ __align__(16) uint8_t g_w2f[(size_t)2 * 16384];

__device__ __forceinline__ uint32_t smem_u32(const void* p) {
    uint32_t a;
    asm("{ .reg .u64 t; cvta.to.shared.u64 t, %1; cvt.u32.u64 %0, t; }"
        : "=r"(a) : "l"(p));
    return a;
}
__device__ __forceinline__ void ldsm4(uint32_t r[4], uint32_t a) {
    asm volatile("ldmatrix.sync.aligned.m8n8.x4.shared.b16 {%0,%1,%2,%3}, [%4];"
        : "=r"(r[0]), "=r"(r[1]), "=r"(r[2]), "=r"(r[3]) : "r"(a));
}
__device__ __forceinline__ void ldsm4t(uint32_t r[4], uint32_t a) {
    asm volatile("ldmatrix.sync.aligned.m8n8.x4.trans.shared.b16 {%0,%1,%2,%3}, [%4];"
        : "=r"(r[0]), "=r"(r[1]), "=r"(r[2]), "=r"(r[3]) : "r"(a));
}
__device__ __forceinline__ void mma16816(float c[4], const uint32_t a[4],
                                         uint32_t b0, uint32_t b1) {
    asm volatile(
        "mma.sync.aligned.m16n8k16.row.col.f32.f16.f16.f32 "
        "{%0,%1,%2,%3}, {%4,%5,%6,%7}, {%8,%9}, {%0,%1,%2,%3};"
        : "+f"(c[0]), "+f"(c[1]), "+f"(c[2]), "+f"(c[3])
        : "r"(a[0]), "r"(a[1]), "r"(a[2]), "r"(a[3]), "r"(b0), "r"(b1));
}
__device__ __forceinline__ void cp_async16(uint32_t s, const void* g) {
    asm volatile("cp.async.cg.shared.global [%0], [%1], 16;" :: "r"(s), "l"(g) : "memory");
}
__device__ __forceinline__ void cp_commit() {
    asm volatile("cp.async.commit_group;" ::: "memory");
}
template <int N> __device__ __forceinline__ void cp_wait() {
    asm volatile("cp.async.wait_group %0;" :: "n"(N) : "memory");
}
__device__ __forceinline__ uint32_t pack_h2(__half a, __half b) {
    __half2 h2 = __halves2half2(a, b);
    return *(uint32_t*)&h2;
}
__device__ __forceinline__ float tanh_fast(float x) {
    float y;
    asm("tanh.approx.f32 %0, %1;" : "=f"(y) : "f"(x));
    return y;
}

// ------- prep: W1 chunk images + W2 image (fp16, swizzled, zero-padded) -------
__global__ void prep_w_kernel(const float* __restrict__ W1t,
                              const float* __restrict__ W1r,
                              const float* __restrict__ W2t,
                              const float* __restrict__ W2r)
{
    if (blockIdx.x < 512) {
        int idx  = blockIdx.x * 256 + threadIdx.x;   // 0..131071
        int np   = idx & 63;
        int k    = (idx >> 6) & 1023;
        int half = idx >> 16;
        const float* W1 = half ? W1r : W1t;

        int n0 = np * 2;
        float w0 = 0.f, w1 = 0.f;
        if (k < K_) {
            if (n0 < H_)     w0 = W1[k * H_ + n0];
            if (n0 + 1 < H_) w1 = W1[k * H_ + n0 + 1];
        }
        int chunk  = k >> 7;
        int kpanel = (k >> 6) & 1;
        int kloc   = k & 63;
        int npanel = n0 >> 6, nloc = n0 & 63;
        uint32_t sw = SW128((uint32_t)(kloc * 128 + nloc * 2));
        size_t o = ((size_t)half * 8 + chunk) * 32768
                 + (size_t)kpanel * 16384 + (size_t)npanel * 8192 + sw;
        *(uint32_t*)(g_wbf + o) = pack_h2(__float2half_rn(w0), __float2half_rn(w1));
    } else {
        int idx  = (blockIdx.x - 512) * 256 + threadIdx.x;   // 0..8191
        int np   = idx & 31;
        int k    = (idx >> 5) & 127;
        int half = idx >> 12;
        const float* W2 = half ? W2r : W2t;
        const int NO = half ? NL : NT;

        int n0 = np * 2;
        float w0 = 0.f, w1 = 0.f;
        if (k < H_) {
            if (n0 < NO)     w0 = W2[k * NO + n0];
            if (n0 + 1 < NO) w1 = W2[k * NO + n0 + 1];
        }
        uint32_t sw = SW128((uint32_t)(k * 128 + n0 * 2));
        *(uint32_t*)(g_w2f + (size_t)half * 16384 + sw) =
            pack_h2(__float2half_rn(w0), __float2half_rn(w1));
    }
}

// -- main: 512 thr, 2(M)x4(N)x2(Ksplit), fp16, 3-stage B, depth-2 A prefetch --
__global__ __launch_bounds__(THREADS, 2)
void parser_hmma_kernel(const float* __restrict__ lstm_out,
                        const int*   __restrict__ stack_index,
                        const int*   __restrict__ stack_len,
                        const int*   __restrict__ buffer_index,
                        const int*   __restrict__ buffer_len,
                        const float* __restrict__ b1t,
                        const float* __restrict__ b2t,
                        const float* __restrict__ b1r,
                        const float* __restrict__ b2r,
                        float* __restrict__ out)
{
    extern __shared__ char smem[];
    const uint32_t sb = smem_u32(smem);
    const int tid  = threadIdx.x;
    const int wid  = tid >> 5;
    const int lane = tid & 31;
    const int ksp  = wid & 1;
    const int wm   = (wid >> 1) & 1;
    const int wn   = wid >> 2;
    const int b0   = blockIdx.x * BM;
    const int half = blockIdx.y;

    int* soff = (int*)(smem + OFF_SOFF);
    if (tid < BM * 4) {
        int row = tid >> 2, s = tid & 3;
        int b = b0 + row;
        int t, valid;
        if (s < 3) { valid = (s < stack_len[b]);  t = stack_index[b * 3 + s]; }
        else       { valid = (0 < buffer_len[b]); t = buffer_index[b]; }
        soff[tid] = valid ? (b * T_ + t) * D_ : -1;
    }
    __syncthreads();

    // A-gather geometry: 2 adjacent k-pairs x 2 m-rows per thread
    const int kpA   = (tid & 31) * 2;        // even k-pair; kpB = kpA+1
    const int mbase = tid >> 5;              // m in {mbase, mbase+16}
    const uint32_t swst0 = (uint32_t)(kpA >> 5) * 4096
                         + SW128((uint32_t)(mbase * 128 + (kpA & 31) * 4));
    const uint32_t swst1 = (uint32_t)(kpA >> 5) * 4096
                         + SW128((uint32_t)((mbase + 16) * 128 + (kpA & 31) * 4));

    // ldmatrix geometry (bases only; swizzles computed inline in compute)
    const int g = lane >> 3, r8 = lane & 7;
    const int arow = wm * 16 + (g & 1) * 8 + r8;
    const int acol = (g >> 1) * 8;
    const int brow = (g & 1) * 8 + r8;
    const int bc0  = ((wn * 32) & 63) + (g >> 1) * 8;
    const uint32_t bnp = (uint32_t)(wn >> 1) * 8192;
    const uint32_t abase = (uint32_t)(arow * 128 + acol * 2);
    const uint32_t bbase = (uint32_t)(brow * 128 + bc0 * 2);

    float acc[4][4];
    #pragma unroll
    for (int j = 0; j < 4; ++j)
        #pragma unroll
        for (int e = 0; e < 4; ++e) acc[j][e] = 0.f;

    auto loadA = [&](int c, float2 (&rv)[4]) {
        #pragma unroll
        for (int it = 0; it < 4; ++it) rv[it] = make_float2(0.f, 0.f);
        #pragma unroll
        for (int kq = 0; kq < 2; ++kq) {            // kpA, kpA+1
            int k = c * KCH + 2 * (kpA + kq);
            if (k < K_) {
                int slot = k / D_;
                int d    = k - slot * D_;
                int offa = soff[mbase * 4 + slot];
                int offb = soff[(mbase + 16) * 4 + slot];
                if (offa >= 0) rv[kq]     = *(const float2*)(lstm_out + offa + d);
                if (offb >= 0) rv[2 + kq] = *(const float2*)(lstm_out + offb + d);
            }
        }
    };
    auto storeA = [&](int c, const float2 (&rv)[4]) {
        char* ah = smem + OFF_A + (c & 1) * 8192;
        uint2 v0, v1;
        v0.x = pack_h2(__float2half_rn(rv[0].x), __float2half_rn(rv[0].y));
        v0.y = pack_h2(__float2half_rn(rv[1].x), __float2half_rn(rv[1].y));
        v1.x = pack_h2(__float2half_rn(rv[2].x), __float2half_rn(rv[2].y));
        v1.y = pack_h2(__float2half_rn(rv[3].x), __float2half_rn(rv[3].y));
        *(uint2*)(ah + swst0) = v0;
        *(uint2*)(ah + swst1) = v1;
    };
    auto fillB = [&](int c, int buf) {
        uint32_t dh = sb + OFF_B + buf * 32768;
        const uint8_t* sh = g_wbf + ((size_t)half * 8 + c) * 32768;
        #pragma unroll
        for (int it = 0; it < 4; ++it) {
            int o = (it * THREADS + tid) * 16;
            cp_async16(dh + o, sh + o);
        }
        cp_commit();
    };
    auto compute = [&](int c, int bufc) {
        uint32_t ah = sb + OFF_A + (c & 1) * 8192 + ksp * 4096;
        uint32_t bh = sb + OFF_B + bufc * 32768 + ksp * 16384 + bnp;
        #pragma unroll
        for (int kk = 0; kk < 4; ++kk) {
            uint32_t Ah[4], Bh[2][4];
            ldsm4(Ah, ah + SW128(abase + (uint32_t)kk * 32));
            ldsm4t(Bh[0], bh + SW128(bbase + (uint32_t)kk * 2048));
            ldsm4t(Bh[1], bh + SW128(bbase + 32 + (uint32_t)kk * 2048));
            #pragma unroll
            for (int j = 0; j < 4; ++j)
                mma16816(acc[j], Ah, Bh[j >> 1][(j & 1) * 2], Bh[j >> 1][(j & 1) * 2 + 1]);
        }
    };

    // prologue: B(0), B(1) in flight; A(0), A(1) to regs (depth-2 prefetch)
    float2 rva[4], rvb[4];
    fillB(0, 0);
    fillB(1, 1);
    loadA(0, rva);
    loadA(1, rvb);

    // fully unrolled mainloop: compile-time buffer indices
    #pragma unroll
    for (int c = 0; c < NCHUNK; ++c) {
        const int bufc = c % 3;
        float2 (&rvc)[4] = (c & 1) ? rvb : rva;
        storeA(c, rvc);
        if (c + 2 < NCHUNK) loadA(c + 2, rvc);   // ~2 compute phases of cover

        cp_wait<1>();            // own copies of B(c) done
        __syncthreads();         // publish fills + all warps done chunk c-1

        if (c + 2 < NCHUNK) fillB(c + 2, (c + 2) % 3);

        compute(c, bufc);
    }
    __syncthreads();   // mainloop done; A+B regions free

    // ---- kick off W2 image fill (16 KB -> OFF_W2I) ----
    {
        uint32_t d = sb + OFF_W2I;
        const uint8_t* s = g_w2f + (size_t)half * 16384;
        int o = tid * 16;
        cp_async16(d + o, s + o);
        cp_async16(d + 8192 + o, s + 8192 + o);
        cp_commit();
    }

    // ---- layer-1 K-split reduction (Rs at OFF_A) ----
    float* Rs = (float*)(smem + OFF_RS);
    const int pairIdx = wid >> 1;
    if (ksp == 1) {
        float* dst = Rs + (pairIdx * 32 + lane) * 16;
        #pragma unroll
        for (int j = 0; j < 4; ++j)
            *(float4*)(dst + j * 4) = make_float4(acc[j][0], acc[j][1], acc[j][2], acc[j][3]);
    }
    __syncthreads();
    const float* b1 = half ? b1r : b1t;
    if (ksp == 0) {
        const float* src = Rs + (pairIdx * 32 + lane) * 16;
        #pragma unroll
        for (int j = 0; j < 4; ++j) {
            float4 v = *(const float4*)(src + j * 4);
            acc[j][0] += v.x; acc[j][1] += v.y; acc[j][2] += v.z; acc[j][3] += v.w;
        }
        // bias + fast tanh -> fp16 Hs panels (cols >= 125 exactly 0)
        #pragma unroll
        for (int j = 0; j < 4; ++j) {
            int row = wm * 16 + (lane >> 2);
            int col = wn * 32 + j * 8 + (lane & 3) * 2;
            float bv0 = (col < H_)     ? __ldg(b1 + col)     : 0.f;
            float bv1 = (col + 1 < H_) ? __ldg(b1 + col + 1) : 0.f;
            uint32_t base = (uint32_t)(col >> 6) * 4096;
            uint32_t sw0 = base + SW128((uint32_t)(row * 128 + (col & 63) * 2));
            uint32_t sw8 = base + SW128((uint32_t)((row + 8) * 128 + (col & 63) * 2));
            *(uint32_t*)(smem + OFF_HF + sw0) =
                pack_h2(__float2half_rn(tanh_fast(acc[j][0] + bv0)),
                        __float2half_rn(tanh_fast(acc[j][1] + bv1)));
            *(uint32_t*)(smem + OFF_HF + sw8) =
                pack_h2(__float2half_rn(tanh_fast(acc[j][2] + bv0)),
                        __float2half_rn(tanh_fast(acc[j][3] + bv1)));
        }
    }
    cp_wait<0>();
    __syncthreads();   // Hs + W2 image ready; Rs reads done

    // ---- layer 2 on tensor pipe: [32 x 64] = Hs[32 x 128] @ W2[128 x 64] ----
    const int m2 = wid & 1;
    const int n4 = (wid >> 1) & 3;
    const int kh = wid >> 3;
    float acc2[2][4];
    #pragma unroll
    for (int j = 0; j < 2; ++j)
        #pragma unroll
        for (int e = 0; e < 4; ++e) acc2[j][e] = 0.f;

    {
        const int arow2 = m2 * 16 + (g & 1) * 8 + r8;
        const int bc2   = n4 * 16 + (g >> 1) * 8;
        uint32_t ha = sb + OFF_HF + (uint32_t)kh * 4096;
        uint32_t wb = sb + OFF_W2I;
        #pragma unroll
        for (int kk = 0; kk < 4; ++kk) {
            int kloc  = kk * 16;
            int kglob = kh * 64 + kloc;
            uint32_t Ah2[4], Bh2[4];
            ldsm4(Ah2, ha + SW128((uint32_t)(arow2 * 128 + (kloc + acol) * 2)));
            ldsm4t(Bh2, wb + SW128((uint32_t)((kglob + brow) * 128 + bc2 * 2)));
            mma16816(acc2[0], Ah2, Bh2[0], Bh2[1]);
            mma16816(acc2[1], Ah2, Bh2[2], Bh2[3]);
        }
    }

    // ---- layer-2 K-half reduction ----
    float* Rs2 = (float*)(smem + OFF_RS);
    const int pair2 = wid & 7;
    if (kh == 1) {
        float* dst = Rs2 + (pair2 * 32 + lane) * 8;
        #pragma unroll
        for (int j = 0; j < 2; ++j)
            *(float4*)(dst + j * 4) = make_float4(acc2[j][0], acc2[j][1], acc2[j][2], acc2[j][3]);
    }
    __syncthreads();

    const int NO = half ? NL : NT;
    const float* b2 = half ? b2r : b2t;
    float* obase = half ? (out + B_TOT * NT) : out;

    if (kh == 0) {
        const float* src = Rs2 + (pair2 * 32 + lane) * 8;
        #pragma unroll
        for (int j = 0; j < 2; ++j) {
            float4 v = *(const float4*)(src + j * 4);
            acc2[j][0] += v.x; acc2[j][1] += v.y; acc2[j][2] += v.z; acc2[j][3] += v.w;
        }
        #pragma unroll
        for (int j = 0; j < 2; ++j) {
            int row = m2 * 16 + (lane >> 2);
            int col = n4 * 16 + j * 8 + (lane & 3) * 2;
            if (col < NO) {
                float bv0 = __ldg(b2 + col);
                obase[(b0 + row) * NO + col]     = tanhf(acc2[j][0] + bv0);
                obase[(b0 + row + 8) * NO + col] = tanhf(acc2[j][2] + bv0);
                if (col + 1 < NO) {
                    float bv1 = __ldg(b2 + col + 1);
                    obase[(b0 + row) * NO + col + 1]     = tanhf(acc2[j][1] + bv1);
                    obase[(b0 + row + 8) * NO + col + 1] = tanhf(acc2[j][3] + bv1);
                }
            }
        }
    }
}

extern "C" void kernel_launch(void* const* d_in, const int* in_sizes, int n_in,
                              void* d_out, int out_size)
{
    const float* lstm_out     = (const float*)d_in[0];
    const int*   stack_index  = (const int*)  d_in[1];
    const int*   stack_len    = (const int*)  d_in[2];
    const int*   buffer_index = (const int*)  d_in[3];
    const int*   buffer_len   = (const int*)  d_in[4];
    const float* W1t          = (const float*)d_in[5];
    const float* b1t          = (const float*)d_in[6];
    const float* W2t          = (const float*)d_in[7];
    const float* b2t          = (const float*)d_in[8];
    const float* W1r          = (const float*)d_in[9];
    const float* b1r          = (const float*)d_in[10];
    const float* W2r          = (const float*)d_in[11];
    const float* b2r          = (const float*)d_in[12];
    float* out = (float*)d_out;

    prep_w_kernel<<<544, 256>>>(W1t, W1r, W2t, W2r);

    cudaFuncSetAttribute(parser_hmma_kernel,
                         cudaFuncAttributeMaxDynamicSharedMemorySize, SMEM_TOTAL);
    dim3 grid(B_TOT / BM, 2);
    parser_hmma_kernel<<<grid, THREADS, SMEM_TOTAL>>>(
        lstm_out, stack_index, stack_len, buffer_index, buffer_len,
        b1t, b2t, b1r, b2r, out);
}